// round 16
// baseline (speedup 1.0000x reference)
#include <cuda_runtime.h>
#include <cuda_fp16.h>
#include <cstdint>

// Fused 2-layer MLP with layer-1 algebraically precomputed per cluster:
//   x·W1 + b1 = H_pre[lab] - p·W1b
//   H_pre[cl] = [feat[cl], ctr[cl]]·W1 + b1   (HMMA prepass)
//   h = relu(H_pre[lab] - p·W1b)              (rank-3 correction, fma.rn.f32x2)
//   o = relu(h @ W2 + b2)                     (HMMA fp16, fp32 acc)
// R16: TPB=256, M=16/warp (8 warps per 128-row tile), 3 CTAs/SM persistent
// -> 24 warps/SM (was 16): +50% latency hiding at ~80 regs/thread.

#define TPB 256
#define CTAS_PER_SM 3
#define GRID_MAIN (148 * CTAS_PER_SM)    // 444: one full wave
#define N_CLUSTERS 16384

#define HS  68             // H_pre smem row stride in u32
#define W2S 68             // W2T row stride in u32

// main-kernel smem layout in u32 words
#define S_H    0                        // [128][68]  gathered H_pre rows (fp16)
#define S_W2   (S_H + 128 * HS)         // [64][68]   W2^T fp16
#define S_W1B  (S_W2 + 64 * W2S)        // [3][128]   fp32 correction rows
#define S_B2   (S_W1B + 384)            // 64 floats
#define S_TOT  (S_B2 + 64)
#define SMEM_BYTES (S_TOT * 4)          // 54016 B -> 3 CTAs/SM = 162 KB

// H_pre table: 16384 rows x 128 halfs = 256B/row, 4MB (L2-resident).
__device__ __align__(16) uint32_t g_hpre[N_CLUSTERS * 64];

// ---------------- helpers ----------------------------------------------------
__device__ __forceinline__ void mma16816(float* d, const uint32_t* a,
                                         uint32_t b0, uint32_t b1) {
    asm volatile(
        "mma.sync.aligned.m16n8k16.row.col.f32.f16.f16.f32 "
        "{%0,%1,%2,%3}, {%4,%5,%6,%7}, {%8,%9}, {%0,%1,%2,%3};"
        : "+f"(d[0]), "+f"(d[1]), "+f"(d[2]), "+f"(d[3])
        : "r"(a[0]), "r"(a[1]), "r"(a[2]), "r"(a[3]), "r"(b0), "r"(b1));
}
__device__ __forceinline__ void ldsm_x4(uint32_t* r, uint32_t addr) {
    asm volatile("ldmatrix.sync.aligned.m8n8.x4.shared.b16 {%0,%1,%2,%3}, [%4];"
                 : "=r"(r[0]), "=r"(r[1]), "=r"(r[2]), "=r"(r[3]) : "r"(addr));
}
__device__ __forceinline__ void cp_async16(uint32_t saddr, const void* gaddr) {
    asm volatile("cp.async.cg.shared.global [%0], [%1], 16;"
                 :: "r"(saddr), "l"(gaddr));
}
#define CP_COMMIT() asm volatile("cp.async.commit_group;" ::: "memory")
#define CP_WAIT0()  asm volatile("cp.async.wait_group 0;" ::: "memory")

__device__ __forceinline__ uint32_t pack2(float x, float y) {
    __half2 h = __floats2half2_rn(x, y);
    return *reinterpret_cast<uint32_t*>(&h);
}
// packed f32x2 (sm_100+ family PTX; NOT arch-'a' gated)
__device__ __forceinline__ uint64_t pack64(float x, float y) {
    uint64_t r;
    asm("mov.b64 %0, {%1, %2};" : "=l"(r) : "f"(x), "f"(y));
    return r;
}
__device__ __forceinline__ uint64_t ffma2(uint64_t a, uint64_t b, uint64_t c) {
    uint64_t d;
    asm("fma.rn.f32x2 %0, %1, %2, %3;" : "=l"(d) : "l"(a), "l"(b), "l"(c));
    return d;
}
__device__ __forceinline__ uint64_t h2f2(uint32_t h) {
    __half2 hh = *reinterpret_cast<__half2*>(&h);
    return pack64(__low2float(hh), __high2float(hh));
}
__device__ __forceinline__ uint32_t cvt_relu_pack(uint64_t v) {
    float lo, hi;
    asm("mov.b64 {%0, %1}, %2;" : "=f"(lo), "=f"(hi) : "l"(v));
    __half2 h = __floats2half2_rn(lo, hi);
    h = __hmax2(h, __float2half2_rn(0.0f));
    return *reinterpret_cast<uint32_t*>(&h);
}

// ------------- HMMA prepass: H_pre = [feat, ctr]·W1 + b1 (unchanged R15) ----
#define PXS 44
#define P_SX   0
#define P_SW   (P_SX + 128 * PXS)
#define P_SWF  (P_SW + 128 * PXS)        // [67][132] fp32 W1 staging
#define P_SB   (P_SWF + 67 * 132)
#define P_TOT  (P_SB + 128)
#define P_SMEM_BYTES (P_TOT * 4)

__global__ __launch_bounds__(256, 2)
void hpre_hmma_kernel(const float* __restrict__ features,
                      const float* __restrict__ centers,
                      const float* __restrict__ W1,
                      const float* __restrict__ b1)
{
    extern __shared__ uint32_t sm[];
    const int tid  = threadIdx.x;
    const int lane = tid & 31;
    const int warp = tid >> 5;
    const int gid  = lane >> 2;
    const int tig  = lane & 3;

    {
        float* sW1f = (float*)&sm[P_SWF];
        for (int idx = tid; idx < 67 * 128; idx += 256) {
            int k  = idx >> 7;
            int nn = idx & 127;
            sW1f[k * 132 + nn] = W1[idx];
        }
    }
    if (tid < 128) ((float*)&sm[P_SB])[tid] = b1[tid];

    const int cl_base = blockIdx.x * 128;
    {
        const int r    = tid >> 1;
        const int half = tid & 1;
        const int cl   = cl_base + r;
        const float4* f4 = (const float4*)(features) + (size_t)cl * 16;
        uint32_t* xrow = &sm[P_SX + r * PXS];
        if (half == 0) {
            #pragma unroll
            for (int i = 0; i < 8; i++) {
                float4 v = __ldg(f4 + i);
                xrow[2 * i]     = pack2(v.x, v.y);
                xrow[2 * i + 1] = pack2(v.z, v.w);
            }
        } else {
            #pragma unroll
            for (int i = 8; i < 16; i++) {
                float4 v = __ldg(f4 + i);
                xrow[2 * i]     = pack2(v.x, v.y);
                xrow[2 * i + 1] = pack2(v.z, v.w);
            }
            float cx = centers[cl * 3 + 0];
            float cy = centers[cl * 3 + 1];
            float cz = centers[cl * 3 + 2];
            xrow[32] = pack2(cx, cy);
            xrow[33] = pack2(cz, 0.0f);
            #pragma unroll
            for (int u = 34; u < 40; u++) xrow[u] = 0u;
        }
    }
    __syncthreads();

    {
        const float* sW1f = (const float*)&sm[P_SWF];
        for (int idx = tid; idx < 128 * PXS; idx += 256) {
            int nn = idx / PXS;
            int ku = idx - nn * PXS;
            int k0 = 2 * ku;
            float v0 = (k0     < 67) ? sW1f[k0 * 132 + nn] : 0.0f;
            float v1 = (k0 + 1 < 67) ? sW1f[(k0 + 1) * 132 + nn] : 0.0f;
            sm[P_SW + idx] = pack2(v0, v1);
        }
    }
    __syncthreads();

    const int m0 = warp * 16;

    uint32_t a[20];
    {
        const uint32_t r0 = (uint32_t)(m0 + gid) * PXS;
        const uint32_t r1 = r0 + 8 * PXS;
        #pragma unroll
        for (int s = 0; s < 5; s++) {
            const uint32_t c0 = 8 * s + tig;
            a[4 * s + 0] = sm[P_SX + r0 + c0];
            a[4 * s + 1] = sm[P_SX + r1 + c0];
            a[4 * s + 2] = sm[P_SX + r0 + c0 + 4];
            a[4 * s + 3] = sm[P_SX + r1 + c0 + 4];
        }
    }

    float acc1[64];
    #pragma unroll
    for (int i = 0; i < 64; i++) acc1[i] = 0.0f;

    #pragma unroll
    for (int j = 0; j < 16; j++) {
        const uint32_t bn = P_SW + (uint32_t)(8 * j + gid) * PXS + tig;
        #pragma unroll
        for (int s = 0; s < 5; s++) {
            uint32_t b0  = sm[bn + 8 * s];
            uint32_t b1r = sm[bn + 8 * s + 4];
            mma16816(&acc1[4 * j], &a[4 * s], b0, b1r);
        }
    }

    {
        const float* sB1f = (const float*)&sm[P_SB];
        uint32_t* h0p = g_hpre + (size_t)(cl_base + m0 + gid) * 64;
        uint32_t* h1p = h0p + 8 * 64;
        #pragma unroll
        for (int j = 0; j < 16; j++) {
            const int nn = 8 * j + 2 * tig;
            float2 bv = *(const float2*)&sB1f[nn];
            const float* c = &acc1[4 * j];
            h0p[4 * j + tig] = pack2(c[0] + bv.x, c[1] + bv.y);
            h1p[4 * j + tig] = pack2(c[2] + bv.x, c[3] + bv.y);
        }
    }
}

// ---------------- main kernel: M=16/warp, TPB=256, persistent ----------------
__global__ __launch_bounds__(TPB, CTAS_PER_SM)
void fused_mlp2_kernel(const int*   __restrict__ labels,
                       const float* __restrict__ points,
                       const float* __restrict__ W1,
                       const float* __restrict__ W2,
                       const float* __restrict__ b2,
                       float*       __restrict__ out,
                       int n)
{
    extern __shared__ uint32_t sm[];

    const int tid  = threadIdx.x;
    const int lane = tid & 31;
    const int warp = tid >> 5;    // 0..7
    const int gid  = lane >> 2;   // 0..7
    const int tig  = lane & 3;    // 0..3

    for (int idx = tid; idx < 64 * W2S; idx += TPB) {
        int nn = idx / W2S;
        int ku = idx - nn * W2S;
        int k0 = 2 * ku;
        float v0 = (k0     < 128) ? W2[k0 * 64 + nn] : 0.0f;
        float v1 = (k0 + 1 < 128) ? W2[(k0 + 1) * 64 + nn] : 0.0f;
        sm[S_W2 + idx] = pack2(v0, v1);
    }
    if (tid < 128) {
        float* w1bf = (float*)&sm[S_W1B];
        w1bf[0 * 128 + tid] = W1[64 * 128 + tid];
        w1bf[1 * 128 + tid] = W1[65 * 128 + tid];
        w1bf[2 * 128 + tid] = W1[66 * 128 + tid];
    }
    if (tid < 64) ((float*)&sm[S_B2])[tid] = b2[tid];
    __syncthreads();   // the only CTA barrier

    const int ntiles = n >> 7;            // 8192
    const int stride = gridDim.x;         // 444
    const int m0 = warp * 16;             // this warp's 16 private rows

    const uint32_t sbase = (uint32_t)__cvta_generic_to_shared(sm);
    const int l7  = lane & 7;
    const int g8  = (lane >> 3) & 1;
    const int g16 = (lane >> 4) & 1;
    const uint32_t hAddr = sbase +
        4u * (S_H + (uint32_t)(m0 + l7 + g8 * 8) * HS + (uint32_t)g16 * 4);
    const uint32_t b2Addr = sbase +
        4u * (S_W2 + (uint32_t)(l7 + g16 * 8) * W2S + (uint32_t)g8 * 4);

    // gather roles: 2 lanes per row (16 rows), 8 x 16B chunks each (256B/row)
    const int rhalf = lane >> 1;          // 0..15
    const int cb    = (lane & 1) * 8;     // chunk base 0/8

    auto gather_tile = [&](int tile) {
        const int tb = tile << 7;
        const int r   = m0 + rhalf;
        const int lab = labels[tb + r];
        const char* src = (const char*)g_hpre + (size_t)lab * 256 + cb * 16;
        uint32_t dst = sbase + 4u * (S_H + (uint32_t)r * HS) + (uint32_t)cb * 16;
        #pragma unroll
        for (int it = 0; it < 8; it++)
            cp_async16(dst + 16u * it, src + 16 * it);
        CP_COMMIT();
    };

    gather_tile(blockIdx.x);
    CP_WAIT0();
    __syncwarp();

    const float* w1bf = (const float*)&sm[S_W1B];
    const float* sB2f = (const float*)&sm[S_B2];

    for (int tile = blockIdx.x; tile < ntiles; tile += stride) {
        const int tile_base = tile << 7;
        const int next = tile + stride;

        // negated point coords, broadcast f32x2 pairs; rows {A=gid, B=gid+8}
        const int rA = tile_base + m0 + gid;
        const int rB = rA + 8;
        const uint64_t npxA = pack64(-points[3 * rA + 0], -points[3 * rA + 0]);
        const uint64_t npyA = pack64(-points[3 * rA + 1], -points[3 * rA + 1]);
        const uint64_t npzA = pack64(-points[3 * rA + 2], -points[3 * rA + 2]);
        const uint64_t npxB = pack64(-points[3 * rB + 0], -points[3 * rB + 0]);
        const uint64_t npyB = pack64(-points[3 * rB + 1], -points[3 * rB + 1]);
        const uint64_t npzB = pack64(-points[3 * rB + 2], -points[3 * rB + 2]);

        float acc2[32];   // [8 n-tiles][4]
        #pragma unroll
        for (int i = 0; i < 32; i++) acc2[i] = 0.0f;

        #pragma unroll
        for (int jp = 0; jp < 8; jp++) {
            const int col = jp * 16 + 2 * tig;
            const uint64_t wx0p = *(const uint64_t*)(w1bf + col);
            const uint64_t wy0p = *(const uint64_t*)(w1bf + 128 + col);
            const uint64_t wz0p = *(const uint64_t*)(w1bf + 256 + col);
            const uint64_t wx1p = *(const uint64_t*)(w1bf + col + 8);
            const uint64_t wy1p = *(const uint64_t*)(w1bf + 128 + col + 8);
            const uint64_t wz1p = *(const uint64_t*)(w1bf + 256 + col + 8);

            uint32_t hp[4];
            ldsm_x4(hp, hAddr + 32u * jp);

            uint32_t ha[4];
            uint64_t v;
            v = h2f2(hp[0]);
            v = ffma2(npxA, wx0p, v);
            v = ffma2(npyA, wy0p, v);
            v = ffma2(npzA, wz0p, v);
            ha[0] = cvt_relu_pack(v);
            v = h2f2(hp[1]);
            v = ffma2(npxB, wx0p, v);
            v = ffma2(npyB, wy0p, v);
            v = ffma2(npzB, wz0p, v);
            ha[1] = cvt_relu_pack(v);
            v = h2f2(hp[2]);
            v = ffma2(npxA, wx1p, v);
            v = ffma2(npyA, wy1p, v);
            v = ffma2(npzA, wz1p, v);
            ha[2] = cvt_relu_pack(v);
            v = h2f2(hp[3]);
            v = ffma2(npxB, wx1p, v);
            v = ffma2(npyB, wy1p, v);
            v = ffma2(npzB, wz1p, v);
            ha[3] = cvt_relu_pack(v);

            #pragma unroll
            for (int jj = 0; jj < 4; jj++) {
                uint32_t bb[4];
                ldsm_x4(bb, b2Addr + (uint32_t)jj * (16 * W2S * 4) + 32u * jp);
                mma16816(&acc2[8 * jj],     ha, bb[0], bb[1]);
                mma16816(&acc2[8 * jj + 4], ha, bb[2], bb[3]);
            }
        }

        if (next < ntiles) gather_tile(next);

        {
            float* o0 = out + (size_t)rA * 64;
            float* o1 = out + (size_t)rB * 64;
            #pragma unroll
            for (int j = 0; j < 8; j++) {
                const int nn = 8 * j + 2 * tig;
                float2 bv = *(const float2*)&sB2f[nn];
                const float* c = &acc2[4 * j];
                float2 v0, v1;
                v0.x = fmaxf(c[0] + bv.x, 0.0f);
                v0.y = fmaxf(c[1] + bv.y, 0.0f);
                v1.x = fmaxf(c[2] + bv.x, 0.0f);
                v1.y = fmaxf(c[3] + bv.y, 0.0f);
                *(float2*)(o0 + nn) = v0;
                *(float2*)(o1 + nn) = v1;
            }
        }

        if (next < ntiles) {
            CP_WAIT0();
            __syncwarp();
        }
    }
}

extern "C" void kernel_launch(void* const* d_in, const int* in_sizes, int n_in,
                              void* d_out, int out_size)
{
    const float* features = (const float*)d_in[0];
    const int*   labels   = (const int*)  d_in[1];
    const float* centers  = (const float*)d_in[2];
    const float* points   = (const float*)d_in[3];
    const float* W1       = (const float*)d_in[4];
    const float* b1       = (const float*)d_in[5];
    const float* W2       = (const float*)d_in[6];
    const float* b2       = (const float*)d_in[7];
    float* out = (float*)d_out;

    int n = in_sizes[1];                  // N_POINTS = 1048576

    cudaFuncSetAttribute(hpre_hmma_kernel,
                         cudaFuncAttributeMaxDynamicSharedMemorySize,
                         (int)P_SMEM_BYTES);
    hpre_hmma_kernel<<<N_CLUSTERS / 128, 256, P_SMEM_BYTES>>>(
        features, centers, W1, b1);

    cudaFuncSetAttribute(fused_mlp2_kernel,
                         cudaFuncAttributeMaxDynamicSharedMemorySize,
                         (int)SMEM_BYTES);

    fused_mlp2_kernel<<<GRID_MAIN, TPB, SMEM_BYTES>>>(
        labels, points, W1, W2, b2, out, n);
}

// round 17
// speedup vs baseline: 1.1141x; 1.1141x over previous
#include <cuda_runtime.h>
#include <cuda_fp16.h>
#include <cstdint>

// Fully fused single kernel:
//   Phase A (CTAs 0..255): H_pre[cl] = [feat[cl], ctr[cl]]·W1 + b1 (HMMA),
//     64 clusters per CTA, then fence + arrive on global counter.
//   Phase B (all 592 CTAs, persistent): h = relu(H_pre[lab] - p·W1b) (f32x2),
//     o = relu(h @ W2 + b2) (HMMA), stride over 128-pt tiles.
// Single launch: removes prepass kernel launch + serialization overhead.

#define TPB 128
#define GRID_MAIN 592                    // 4 CTAs/SM x 148 SMs: one full wave
#define PP_CTAS 256                      // prepass roles (64 clusters each)
#define N_CLUSTERS 16384

#define HS  68             // H_pre smem row stride in u32
#define W2S 68             // W2T row stride in u32

// main smem layout in u32 words
#define S_H    0                        // [128][68]  gathered H_pre rows (fp16)
#define S_W2   (S_H + 128 * HS)         // [64][68]   W2^T fp16  (offset 34816B)
#define S_W1B  (S_W2 + 64 * W2S)        // [3][128]   fp32 correction rows
#define S_B2   (S_W1B + 384)            // 64 floats
#define S_TOT  (S_B2 + 64)
#define SMEM_BYTES (S_TOT * 4)          // 54016 B -> 4 CTAs/SM

// prepass scratch (u32 offsets), entirely below S_W2 (34816B = 8704 u32)
#define PP_X   0                        // [64][44]  X fp16 (clusters)
#define PP_W   (PP_X + 64 * 44)         // [128][44] W1T fp16 (88 halfs/row)
#define PP_B1  (PP_W + 128 * 44)        // 128 floats b1
// PP_B1 + 128 = 8576 u32 = 34304 B  <= 34816 OK

// H_pre table: 16384 rows x 128 halfs = 256B/row, 4MB (L2-resident).
__device__ __align__(16) uint32_t g_hpre[N_CLUSTERS * 64];
__device__ int g_count = 0;   // prepass CTAs completed
__device__ int g_done  = 0;   // CTAs finished (for counter reset)

// ---------------- helpers ----------------------------------------------------
__device__ __forceinline__ void mma16816(float* d, const uint32_t* a,
                                         uint32_t b0, uint32_t b1) {
    asm volatile(
        "mma.sync.aligned.m16n8k16.row.col.f32.f16.f16.f32 "
        "{%0,%1,%2,%3}, {%4,%5,%6,%7}, {%8,%9}, {%0,%1,%2,%3};"
        : "+f"(d[0]), "+f"(d[1]), "+f"(d[2]), "+f"(d[3])
        : "r"(a[0]), "r"(a[1]), "r"(a[2]), "r"(a[3]), "r"(b0), "r"(b1));
}
__device__ __forceinline__ void ldsm_x4(uint32_t* r, uint32_t addr) {
    asm volatile("ldmatrix.sync.aligned.m8n8.x4.shared.b16 {%0,%1,%2,%3}, [%4];"
                 : "=r"(r[0]), "=r"(r[1]), "=r"(r[2]), "=r"(r[3]) : "r"(addr));
}
__device__ __forceinline__ void cp_async16(uint32_t saddr, const void* gaddr) {
    asm volatile("cp.async.cg.shared.global [%0], [%1], 16;"
                 :: "r"(saddr), "l"(gaddr));
}
#define CP_COMMIT() asm volatile("cp.async.commit_group;" ::: "memory")
#define CP_WAIT0()  asm volatile("cp.async.wait_group 0;" ::: "memory")

__device__ __forceinline__ uint32_t pack2(float x, float y) {
    __half2 h = __floats2half2_rn(x, y);
    return *reinterpret_cast<uint32_t*>(&h);
}
__device__ __forceinline__ uint64_t pack64(float x, float y) {
    uint64_t r;
    asm("mov.b64 %0, {%1, %2};" : "=l"(r) : "f"(x), "f"(y));
    return r;
}
__device__ __forceinline__ uint64_t ffma2(uint64_t a, uint64_t b, uint64_t c) {
    uint64_t d;
    asm("fma.rn.f32x2 %0, %1, %2, %3;" : "=l"(d) : "l"(a), "l"(b), "l"(c));
    return d;
}
__device__ __forceinline__ uint64_t h2f2(uint32_t h) {
    __half2 hh = *reinterpret_cast<__half2*>(&h);
    return pack64(__low2float(hh), __high2float(hh));
}
__device__ __forceinline__ uint32_t cvt_relu_pack(uint64_t v) {
    float lo, hi;
    asm("mov.b64 {%0, %1}, %2;" : "=f"(lo), "=f"(hi) : "l"(v));
    __half2 h = __floats2half2_rn(lo, hi);
    h = __hmax2(h, __float2half2_rn(0.0f));
    return *reinterpret_cast<uint32_t*>(&h);
}

// ---------------- fused kernel ------------------------------------------------
__global__ __launch_bounds__(TPB, 4)
void fused_all_kernel(const float* __restrict__ features,
                      const int*   __restrict__ labels,
                      const float* __restrict__ centers,
                      const float* __restrict__ points,
                      const float* __restrict__ W1,
                      const float* __restrict__ b1,
                      const float* __restrict__ W2,
                      const float* __restrict__ b2,
                      float*       __restrict__ out,
                      int n)
{
    extern __shared__ uint32_t sm[];

    const int tid  = threadIdx.x;
    const int lane = tid & 31;
    const int warp = tid >> 5;    // 0..3
    const int gid  = lane >> 2;   // 0..7
    const int tig  = lane & 3;    // 0..3

    // ================= Phase A: prepass (CTAs 0..255) ========================
    if (blockIdx.x < PP_CTAS) {
        // zero W1T pad region (ku 32..43 for all 128 n-rows)
        for (int idx = tid; idx < 128 * 12; idx += TPB) {
            int nn = idx / 12, ku = 32 + idx - (idx / 12) * 12;
            sm[PP_W + nn * 44 + ku] = 0u;
        }
        __syncthreads();

        // W1T fp16 via coalesced fp32 reads + b16 smem stores
        {
            __half* w1t = (__half*)&sm[PP_W];
            for (int idx = tid; idx < 67 * 128; idx += TPB) {
                int k  = idx >> 7;
                int nn = idx & 127;
                w1t[nn * 88 + k] = __float2half(W1[idx]);
            }
        }
        if (tid < 128) ((float*)&sm[PP_B1])[tid] = b1[tid];

        // X: 64 clusters, 2 threads per row
        const int cl_base = blockIdx.x * 64;
        {
            const int r    = tid >> 1;
            const int half = tid & 1;
            const int cl   = cl_base + r;
            const float4* f4 = (const float4*)(features) + (size_t)cl * 16;
            uint32_t* xrow = &sm[PP_X + r * 44];
            if (half == 0) {
                #pragma unroll
                for (int i = 0; i < 8; i++) {
                    float4 v = __ldg(f4 + i);
                    xrow[2 * i]     = pack2(v.x, v.y);
                    xrow[2 * i + 1] = pack2(v.z, v.w);
                }
            } else {
                #pragma unroll
                for (int i = 8; i < 16; i++) {
                    float4 v = __ldg(f4 + i);
                    xrow[2 * i]     = pack2(v.x, v.y);
                    xrow[2 * i + 1] = pack2(v.z, v.w);
                }
                xrow[32] = pack2(centers[cl * 3 + 0], centers[cl * 3 + 1]);
                xrow[33] = pack2(centers[cl * 3 + 2], 0.0f);
                #pragma unroll
                for (int u = 34; u < 40; u++) xrow[u] = 0u;
            }
        }
        __syncthreads();

        // HMMA: M=64 (warp w -> rows 16w..16w+15), N=128, K=80
        const int m0 = warp * 16;
        uint32_t a[20];
        {
            const uint32_t r0 = (uint32_t)(m0 + gid) * 44;
            const uint32_t r1 = r0 + 8 * 44;
            #pragma unroll
            for (int s = 0; s < 5; s++) {
                const uint32_t c0 = 8 * s + tig;
                a[4 * s + 0] = sm[PP_X + r0 + c0];
                a[4 * s + 1] = sm[PP_X + r1 + c0];
                a[4 * s + 2] = sm[PP_X + r0 + c0 + 4];
                a[4 * s + 3] = sm[PP_X + r1 + c0 + 4];
            }
        }
        float acc1[64];
        #pragma unroll
        for (int i = 0; i < 64; i++) acc1[i] = 0.0f;
        #pragma unroll
        for (int j = 0; j < 16; j++) {
            const uint32_t bn = PP_W + (uint32_t)(8 * j + gid) * 44 + tig;
            #pragma unroll
            for (int s = 0; s < 5; s++) {
                uint32_t b0  = sm[bn + 8 * s];
                uint32_t b1r = sm[bn + 8 * s + 4];
                mma16816(&acc1[4 * j], &a[4 * s], b0, b1r);
            }
        }
        {
            const float* sB1f = (const float*)&sm[PP_B1];
            uint32_t* h0p = g_hpre + (size_t)(cl_base + m0 + gid) * 64;
            uint32_t* h1p = h0p + 8 * 64;
            #pragma unroll
            for (int j = 0; j < 16; j++) {
                const int nn = 8 * j + 2 * tig;
                float2 bv = *(const float2*)&sB1f[nn];
                const float* c = &acc1[4 * j];
                h0p[4 * j + tig] = pack2(c[0] + bv.x, c[1] + bv.y);
                h1p[4 * j + tig] = pack2(c[2] + bv.x, c[3] + bv.y);
            }
        }
        __threadfence();          // H_pre visible device-wide
        __syncthreads();          // all warps' stores done before arrive
        if (tid == 0) atomicAdd(&g_count, 1);
        __syncthreads();          // PP_* smem dead before S_H gathers
    }

    // ============ main smem preload (independent of H_pre) ===================
    for (int idx = tid; idx < 64 * W2S; idx += TPB) {
        int nn = idx / W2S;
        int ku = idx - nn * W2S;
        int k0 = 2 * ku;
        float v0 = (k0     < 128) ? W2[k0 * 64 + nn] : 0.0f;
        float v1 = (k0 + 1 < 128) ? W2[(k0 + 1) * 64 + nn] : 0.0f;
        sm[S_W2 + idx] = pack2(v0, v1);
    }
    {
        float* w1bf = (float*)&sm[S_W1B];
        w1bf[0 * 128 + tid] = W1[64 * 128 + tid];
        w1bf[1 * 128 + tid] = W1[65 * 128 + tid];
        w1bf[2 * 128 + tid] = W1[66 * 128 + tid];
    }
    if (tid < 64) ((float*)&sm[S_B2])[tid] = b2[tid];

    // ============ wait for all prepass tiles =================================
    if (tid == 0) {
        while (atomicAdd(&g_count, 0) < PP_CTAS) __nanosleep(128);
    }
    __syncthreads();
    __threadfence();   // acquire side

    // ================= Phase B: main loop (R15 structure) ====================
    const int ntiles = n >> 7;            // 8192
    const int stride = gridDim.x;         // 592
    const int m0 = warp * 32;             // this warp's 32 private rows

    const uint32_t sbase = (uint32_t)__cvta_generic_to_shared(sm);
    const int l7  = lane & 7;
    const int g8  = (lane >> 3) & 1;
    const int g16 = (lane >> 4) & 1;
    const uint32_t hAddr = sbase +
        4u * (S_H + (uint32_t)(m0 + l7 + g8 * 8) * HS + (uint32_t)g16 * 4);
    const uint32_t b2Addr = sbase +
        4u * (S_W2 + (uint32_t)(l7 + g16 * 8) * W2S + (uint32_t)g8 * 4);

    const int rhalf = lane >> 1;          // 0..15
    const int cb    = (lane & 1) * 8;     // chunk base 0/8

    auto gather_tile = [&](int tile) {
        const int tb = tile << 7;
        #pragma unroll
        for (int half = 0; half < 2; half++) {
            const int r   = m0 + 16 * half + rhalf;
            const int lab = labels[tb + r];
            const char* src = (const char*)g_hpre + (size_t)lab * 256 + cb * 16;
            uint32_t dst = sbase + 4u * (S_H + (uint32_t)r * HS) + (uint32_t)cb * 16;
            #pragma unroll
            for (int it = 0; it < 8; it++)
                cp_async16(dst + 16u * it, src + 16 * it);
        }
        CP_COMMIT();
    };

    gather_tile(blockIdx.x);
    CP_WAIT0();
    __syncwarp();

    const float* w1bf = (const float*)&sm[S_W1B];
    const float* sB2f = (const float*)&sm[S_B2];

    for (int tile = blockIdx.x; tile < ntiles; tile += stride) {
        const int tile_base = tile << 7;
        const int next = tile + stride;

        uint64_t npx[4], npy[4], npz[4];
        #pragma unroll
        for (int mt = 0; mt < 2; mt++) {
            const int rA = tile_base + m0 + mt * 16 + gid;
            const int rB = rA + 8;
            float ax = -points[3 * rA + 0], ay = -points[3 * rA + 1], az = -points[3 * rA + 2];
            float bx = -points[3 * rB + 0], by = -points[3 * rB + 1], bz = -points[3 * rB + 2];
            npx[mt * 2 + 0] = pack64(ax, ax);
            npy[mt * 2 + 0] = pack64(ay, ay);
            npz[mt * 2 + 0] = pack64(az, az);
            npx[mt * 2 + 1] = pack64(bx, bx);
            npy[mt * 2 + 1] = pack64(by, by);
            npz[mt * 2 + 1] = pack64(bz, bz);
        }

        float acc2[64];
        #pragma unroll
        for (int i = 0; i < 64; i++) acc2[i] = 0.0f;

        #pragma unroll
        for (int jp = 0; jp < 8; jp++) {
            const int col = jp * 16 + 2 * tig;
            const uint64_t wx0p = *(const uint64_t*)(w1bf + col);
            const uint64_t wy0p = *(const uint64_t*)(w1bf + 128 + col);
            const uint64_t wz0p = *(const uint64_t*)(w1bf + 256 + col);
            const uint64_t wx1p = *(const uint64_t*)(w1bf + col + 8);
            const uint64_t wy1p = *(const uint64_t*)(w1bf + 128 + col + 8);
            const uint64_t wz1p = *(const uint64_t*)(w1bf + 256 + col + 8);

            uint32_t ha[8];
            #pragma unroll
            for (int mt = 0; mt < 2; mt++) {
                uint32_t hp[4];
                ldsm_x4(hp, hAddr + (uint32_t)mt * (16 * HS * 4) + 32u * jp);
                const int rA = mt * 2, rB = mt * 2 + 1;
                uint64_t v;
                v = h2f2(hp[0]);
                v = ffma2(npx[rA], wx0p, v);
                v = ffma2(npy[rA], wy0p, v);
                v = ffma2(npz[rA], wz0p, v);
                ha[mt * 4 + 0] = cvt_relu_pack(v);
                v = h2f2(hp[1]);
                v = ffma2(npx[rB], wx0p, v);
                v = ffma2(npy[rB], wy0p, v);
                v = ffma2(npz[rB], wz0p, v);
                ha[mt * 4 + 1] = cvt_relu_pack(v);
                v = h2f2(hp[2]);
                v = ffma2(npx[rA], wx1p, v);
                v = ffma2(npy[rA], wy1p, v);
                v = ffma2(npz[rA], wz1p, v);
                ha[mt * 4 + 2] = cvt_relu_pack(v);
                v = h2f2(hp[3]);
                v = ffma2(npx[rB], wx1p, v);
                v = ffma2(npy[rB], wy1p, v);
                v = ffma2(npz[rB], wz1p, v);
                ha[mt * 4 + 3] = cvt_relu_pack(v);
            }

            #pragma unroll
            for (int jj = 0; jj < 4; jj++) {
                uint32_t bb[4];
                ldsm_x4(bb, b2Addr + (uint32_t)jj * (16 * W2S * 4) + 32u * jp);
                mma16816(&acc2[ 0 + 8*jj],     &ha[0], bb[0], bb[1]);
                mma16816(&acc2[ 0 + 8*jj + 4], &ha[0], bb[2], bb[3]);
                mma16816(&acc2[32 + 8*jj],     &ha[4], bb[0], bb[1]);
                mma16816(&acc2[32 + 8*jj + 4], &ha[4], bb[2], bb[3]);
            }
        }

        if (next < ntiles) gather_tile(next);

        {
            #pragma unroll
            for (int mt = 0; mt < 2; mt++) {
                float* o0 = out + (size_t)(tile_base + m0 + 16 * mt + gid) * 64;
                float* o1 = o0 + 8 * 64;
                #pragma unroll
                for (int j = 0; j < 8; j++) {
                    const int nn = 8 * j + 2 * tig;
                    float2 bv = *(const float2*)&sB2f[nn];
                    const float* c = &acc2[mt * 32 + 4 * j];
                    float2 v0, v1;
                    v0.x = fmaxf(c[0] + bv.x, 0.0f);
                    v0.y = fmaxf(c[1] + bv.y, 0.0f);
                    v1.x = fmaxf(c[2] + bv.x, 0.0f);
                    v1.y = fmaxf(c[3] + bv.y, 0.0f);
                    *(float2*)(o0 + nn) = v0;
                    *(float2*)(o1 + nn) = v1;
                }
            }
        }

        if (next < ntiles) {
            CP_WAIT0();
            __syncwarp();
        }
    }

    // ============ counter reset for graph replays ============================
    __syncthreads();
    if (tid == 0) {
        int o = atomicAdd(&g_done, 1);
        if (o == (int)gridDim.x - 1) {
            atomicExch(&g_count, 0);
            atomicExch(&g_done, 0);
        }
    }
}

extern "C" void kernel_launch(void* const* d_in, const int* in_sizes, int n_in,
                              void* d_out, int out_size)
{
    const float* features = (const float*)d_in[0];
    const int*   labels   = (const int*)  d_in[1];
    const float* centers  = (const float*)d_in[2];
    const float* points   = (const float*)d_in[3];
    const float* W1       = (const float*)d_in[4];
    const float* b1       = (const float*)d_in[5];
    const float* W2       = (const float*)d_in[6];
    const float* b2       = (const float*)d_in[7];
    float* out = (float*)d_out;

    int n = in_sizes[1];                  // N_POINTS = 1048576

    cudaFuncSetAttribute(fused_all_kernel,
                         cudaFuncAttributeMaxDynamicSharedMemorySize,
                         (int)SMEM_BYTES);

    fused_all_kernel<<<GRID_MAIN, TPB, SMEM_BYTES>>>(
        features, labels, centers, points, W1, b1, W2, b2, out, n);
}